// round 1
// baseline (speedup 1.0000x reference)
#include <cuda_runtime.h>

// ---------------- problem constants ----------------
constexpr int B    = 64;
constexpr int N    = 512;
constexpr int FGAT = 128;   // GAT_DIM
constexpr int HID  = 256;
constexpr int R    = B * N; // 32768 rows

// ---------------- device scratch (no allocations allowed) ----------------
__device__ float g_Wh[R * FGAT];          // 16 MB  — current layer's Wh
__device__ float g_heads[R * 3 * FGAT];   // 50 MB  — concat of 3 heads
__device__ float g_x[R * FGAT];           // 16 MB  — output-GAT result (post-elu)
__device__ float g_src[R];
__device__ float g_dst[R];
__device__ float g_m[R];
__device__ float g_rz[R];

__device__ __forceinline__ float lrelu02(float x) { return x > 0.f ? x : 0.2f * x; }
__device__ __forceinline__ float elu1(float x)    { return x > 0.f ? x : expm1f(x); }

// ---------------- K1: Wh = h @ W ; src = Wh@a1 ; dst = Wh@a2 ----------------
// one block per row, 128 threads (one per output feature)
__global__ void k_proj(const float* __restrict__ hx, int Fin,
                       const float* __restrict__ W, const float* __restrict__ a)
{
    __shared__ float hs[384];
    __shared__ float red1[4], red2[4];
    int r = blockIdx.x;
    int f = threadIdx.x;

    const float* h = (Fin == 34) ? (hx + (size_t)r * 34)
                                 : (g_heads + (size_t)r * 384);
    for (int k = f; k < Fin; k += 128) hs[k] = h[k];
    __syncthreads();

    float acc = 0.f;
    for (int k = 0; k < Fin; ++k) acc = fmaf(hs[k], W[k * FGAT + f], acc);
    g_Wh[(size_t)r * FGAT + f] = acc;

    float v1 = acc * a[f];
    float v2 = acc * a[FGAT + f];
#pragma unroll
    for (int o = 16; o; o >>= 1) {
        v1 += __shfl_xor_sync(0xffffffffu, v1, o);
        v2 += __shfl_xor_sync(0xffffffffu, v2, o);
    }
    if ((f & 31) == 0) { red1[f >> 5] = v1; red2[f >> 5] = v2; }
    __syncthreads();
    if (f == 0) {
        g_src[r] = red1[0] + red1[1] + red1[2] + red1[3];
        g_dst[r] = red2[0] + red2[1] + red2[2] + red2[3];
    }
}

// ---------------- K2: per-row softmax stats m_i, 1/Z_i ----------------
// one block per row (b,i), 512 threads (one per column j)
__global__ void k_stats(const int* __restrict__ adj)
{
    int r = blockIdx.x;          // b*512 + i
    int b = r >> 9;
    int j = threadIdx.x;

    float si = g_src[r];
    int   av = adj[(size_t)r * 512 + j];
    float e  = lrelu02(si + g_dst[(b << 9) + j]);
    float sc = (av > 0) ? e : -9e15f;

    __shared__ float red[16];
    __shared__ float m_sh;
    int lane = j & 31, wid = j >> 5;

    float v = sc;
#pragma unroll
    for (int o = 16; o; o >>= 1) v = fmaxf(v, __shfl_xor_sync(0xffffffffu, v, o));
    if (lane == 0) red[wid] = v;
    __syncthreads();
    if (j == 0) {
        float mm = red[0];
#pragma unroll
        for (int k = 1; k < 16; ++k) mm = fmaxf(mm, red[k]);
        m_sh = mm;
    }
    __syncthreads();

    float p = __expf(sc - m_sh);
#pragma unroll
    for (int o = 16; o; o >>= 1) p += __shfl_xor_sync(0xffffffffu, p, o);
    if (lane == 0) red[wid] = p;
    __syncthreads();
    if (j == 0) {
        float z = 0.f;
#pragma unroll
        for (int k = 0; k < 16; ++k) z += red[k];
        g_m[r]  = m_sh;
        g_rz[r] = 1.f / z;
    }
}

// ---------------- K3: h'[i,f] = elu( (1/Z_i) * sum_j p(i,j) * Wh[j,f] ) ----------------
// Output tile 64 rows x 128 cols per CTA, 256 threads.
// Thread (fg = tid&31, ig = tid>>5) owns f = fg*4..fg*4+3, i = ig*8..ig*8+7  -> 32 accs.
constexpr int TI = 64, TJ = 32;

__global__ __launch_bounds__(256) void k_agg(const int* __restrict__ adj, int layer)
{
    __shared__ float dstS[512];
    __shared__ float srcS[TI], mS[TI], rZS[TI];
    __shared__ int   adjS[TI][TJ + 1];   // padded: conflict-free
    __shared__ float WhS[TJ][128];
    __shared__ float PS[TJ][TI];         // transposed P tile

    int b   = blockIdx.y;
    int i0  = blockIdx.x * TI;
    int tid = threadIdx.x;
    int fg  = tid & 31;
    int ig  = tid >> 5;

    for (int k = tid; k < 512; k += 256) dstS[k] = g_dst[(b << 9) + k];
    if (tid < TI) {
        int r = (b << 9) + i0 + tid;
        srcS[tid] = g_src[r];
        mS[tid]   = g_m[r];
        rZS[tid]  = g_rz[r];
    }

    float acc[8][4];
#pragma unroll
    for (int rr = 0; rr < 8; ++rr)
#pragma unroll
        for (int c = 0; c < 4; ++c) acc[rr][c] = 0.f;

    const size_t adj_base = ((size_t)(b << 9) + i0) * 512;
    const float4* Whg = reinterpret_cast<const float4*>(g_Wh) + (size_t)(b << 9) * 32;

    for (int t = 0; t < N / TJ; ++t) {
        const int tj0 = t * TJ;
        __syncthreads();   // previous main loop done

        // stage adj tile (coalesced along j)
        for (int e = tid; e < TI * TJ; e += 256) {
            int ii = e >> 5, jj = e & 31;
            adjS[ii][jj] = adj[adj_base + (size_t)ii * 512 + tj0 + jj];
        }
        // stage Wh tile [TJ x 128] via float4
        for (int e = tid; e < TJ * 32; e += 256) {
            int jj = e >> 5, c = e & 31;
            reinterpret_cast<float4*>(WhS)[e] = Whg[(size_t)(tj0 + jj) * 32 + c];
        }
        __syncthreads();

        // compute P tile transposed: PS[j][i] = exp(score(i,j) - m_i)
        {
            int ii = tid & 63;
            int jg = tid >> 6;
            float si = srcS[ii];
            float mi = mS[ii];
#pragma unroll
            for (int rr = 0; rr < 8; ++rr) {
                int j = jg * 8 + rr;
                float e2 = lrelu02(si + dstS[tj0 + j]);
                float sc = (adjS[ii][j] > 0) ? e2 : -9e15f;
                PS[j][ii] = __expf(sc - mi);
            }
        }
        __syncthreads();

        // main FMA loop: 3x LDS.128 per 32 FFMA
#pragma unroll
        for (int j = 0; j < TJ; ++j) {
            float4 w  = *reinterpret_cast<const float4*>(&WhS[j][fg * 4]);
            float4 p0 = *reinterpret_cast<const float4*>(&PS[j][ig * 8]);
            float4 p1 = *reinterpret_cast<const float4*>(&PS[j][ig * 8 + 4]);
            float pv[8] = {p0.x, p0.y, p0.z, p0.w, p1.x, p1.y, p1.z, p1.w};
            float wv[4] = {w.x, w.y, w.z, w.w};
#pragma unroll
            for (int rr = 0; rr < 8; ++rr)
#pragma unroll
                for (int c = 0; c < 4; ++c)
                    acc[rr][c] = fmaf(pv[rr], wv[c], acc[rr][c]);
        }
    }

    // epilogue: normalize by 1/Z, elu, store
    float* outp = (layer < 3) ? g_heads : g_x;
    int ld      = (layer < 3) ? 384 : 128;
    int col0    = (layer < 3) ? layer * 128 + fg * 4 : fg * 4;
#pragma unroll
    for (int rr = 0; rr < 8; ++rr) {
        int i   = i0 + ig * 8 + rr;
        float s = rZS[ig * 8 + rr];
        float4 o;
        o.x = elu1(acc[rr][0] * s);
        o.y = elu1(acc[rr][1] * s);
        o.z = elu1(acc[rr][2] * s);
        o.w = elu1(acc[rr][3] * s);
        *reinterpret_cast<float4*>(&outp[((size_t)(b << 9) + i) * ld + col0]) = o;
    }
}

// ---------------- K4: out = lrelu( x @ Wc + bc ) ----------------
// one block per row, 256 threads (one per output channel)
__global__ void k_final(const float* __restrict__ Wc, const float* __restrict__ bc,
                        float* __restrict__ out)
{
    __shared__ float xs[128];
    int r = blockIdx.x;
    int h = threadIdx.x;
    if (h < 128) xs[h] = g_x[(size_t)r * 128 + h];
    __syncthreads();
    float acc = bc[h];
#pragma unroll 8
    for (int k = 0; k < 128; ++k) acc = fmaf(xs[k], Wc[k * 256 + h], acc);
    out[(size_t)r * 256 + h] = lrelu02(acc);
}

// ---------------- launch ----------------
extern "C" void kernel_launch(void* const* d_in, const int* in_sizes, int n_in,
                              void* d_out, int out_size)
{
    (void)in_sizes; (void)n_in; (void)out_size;
    const float* compound = (const float*)d_in[0];   // [64,512,34]
    const int*   adj      = (const int*)d_in[1];     // [64,512,512]
    const float* Wst      = (const float*)d_in[2];   // [3,34,128]
    const float* ast      = (const float*)d_in[3];   // [3,256,1]
    const float* Wout     = (const float*)d_in[4];   // [384,128]
    const float* aout     = (const float*)d_in[5];   // [256,1]
    const float* Wc       = (const float*)d_in[6];   // [128,256]
    const float* bc       = (const float*)d_in[7];   // [256]
    float* out = (float*)d_out;                      // [64,512,256]

    dim3 agg_grid(N / TI, B);

    for (int l = 0; l < 3; ++l) {
        k_proj<<<R, 128>>>(compound, 34, Wst + l * 34 * FGAT, ast + l * 2 * FGAT);
        k_stats<<<R, 512>>>(adj);
        k_agg<<<agg_grid, 256>>>(adj, l);
    }
    // output GAT layer on concatenated heads
    k_proj<<<R, 128>>>(compound /*unused for Fin=384*/, 384, Wout, aout);
    k_stats<<<R, 512>>>(adj);
    k_agg<<<agg_grid, 256>>>(adj, 3);

    k_final<<<R, 256>>>(Wc, bc, out);
}

// round 2
// speedup vs baseline: 1.3611x; 1.3611x over previous
#include <cuda_runtime.h>

typedef unsigned long long ull;

// ---------------- problem constants ----------------
constexpr int B    = 64;
constexpr int N    = 512;
constexpr int FGAT = 128;
constexpr int R    = B * N;      // 32768 rows

// ---------------- device scratch ----------------
__device__ float g_Wh3[(size_t)4 * R * 128];     // 64 MB: Wh per layer (0..2) + out-layer (3)
__device__ float g_heads[(size_t)R * 384];       // 50 MB
__device__ float g_x[(size_t)R * 128];           // 16 MB
__device__ float g_src3[4 * R];
__device__ float g_dst3[4 * R];
__device__ float g_m3[4 * R];
__device__ float g_rz3[4 * R];

__device__ __forceinline__ float lrelu02(float x) { return x > 0.f ? x : 0.2f * x; }
__device__ __forceinline__ float elu1(float x)    { return x > 0.f ? x : expm1f(x); }

// f32x2 packed FMA helpers
__device__ __forceinline__ void fma2(ull& d, ull a, ull b) {
    asm("fma.rn.f32x2 %0, %1, %2, %3;" : "=l"(d) : "l"(a), "l"(b), "l"(d));
}
__device__ __forceinline__ ull pack2(float x) {
    ull r; asm("mov.b64 %0, {%1, %1};" : "=l"(r) : "f"(x)); return r;
}
__device__ __forceinline__ void unpack2(ull v, float& lo, float& hi) {
    asm("mov.b64 {%0, %1}, %2;" : "=f"(lo), "=f"(hi) : "l"(v));
}
union F4U { float4 f; ull u[2]; };

// ============ K1: blocked GEMM  Wh = X @ W,  fused src/dst = Wh @ a1/a2 ============
// CTA tile: 64 rows x 128 cols, 256 threads; thread (fg=tid&31, ig=tid>>5)
// owns rows ig*8..+7 (packed pairs) x cols fg*4..+3.
template<int FIN, int TK>
__global__ __launch_bounds__(256) void k_proj(
    const float* __restrict__ X, int ldx,
    const float* __restrict__ Wbase, const float* __restrict__ abase,
    float* __restrict__ Whout, float* __restrict__ srcout, float* __restrict__ dstout)
{
    __shared__ __align__(16) float WtS[TK][128];
    __shared__ __align__(16) float htT[TK][68];
    __shared__ float aS[256];

    const int l   = blockIdx.z;
    const float* W = Wbase + (size_t)l * FIN * 128;
    const float* a = abase + l * 256;
    float* Wh   = Whout + (size_t)l * R * 128;
    float* srcp = srcout + (size_t)l * R;
    float* dstp = dstout + (size_t)l * R;

    const int r0  = blockIdx.y * 512 + blockIdx.x * 64;
    const int tid = threadIdx.x;
    const int fg  = tid & 31;
    const int ig  = tid >> 5;

    aS[tid] = a[tid];

    ull acc2[4][4];
#pragma unroll
    for (int rp = 0; rp < 4; ++rp)
#pragma unroll
        for (int c = 0; c < 4; ++c) acc2[rp][c] = 0ull;

    for (int k0 = 0; k0 < FIN; k0 += TK) {
        __syncthreads();
        // stage W tile [TK x 128]
        for (int e = tid; e < TK * 32; e += 256) {
            int k = e >> 5, c = e & 31;
            *reinterpret_cast<float4*>(&WtS[k][c * 4]) =
                *reinterpret_cast<const float4*>(&W[(size_t)(k0 + k) * 128 + c * 4]);
        }
        // stage X^T tile [TK x 64]
        for (int e = tid; e < 64 * TK; e += 256) {
            int ii = e / TK, k = e - ii * TK;
            htT[k][ii] = X[(size_t)(r0 + ii) * ldx + k0 + k];
        }
        __syncthreads();

#pragma unroll 8
        for (int k = 0; k < TK; ++k) {
            float4 w = *reinterpret_cast<const float4*>(&WtS[k][fg * 4]);
            ull w0 = pack2(w.x), w1 = pack2(w.y), w2 = pack2(w.z), w3 = pack2(w.w);
            F4U p0, p1;
            p0.f = *reinterpret_cast<const float4*>(&htT[k][ig * 8]);
            p1.f = *reinterpret_cast<const float4*>(&htT[k][ig * 8 + 4]);
            ull pr[4] = {p0.u[0], p0.u[1], p1.u[0], p1.u[1]};
#pragma unroll
            for (int rp = 0; rp < 4; ++rp) {
                fma2(acc2[rp][0], pr[rp], w0);
                fma2(acc2[rp][1], pr[rp], w1);
                fma2(acc2[rp][2], pr[rp], w2);
                fma2(acc2[rp][3], pr[rp], w3);
            }
        }
    }

    // epilogue: unpack, store Wh, fused src/dst warp reductions
    float val[8][4];
#pragma unroll
    for (int rp = 0; rp < 4; ++rp)
#pragma unroll
        for (int c = 0; c < 4; ++c)
            unpack2(acc2[rp][c], val[2 * rp][c], val[2 * rp + 1][c]);

    float a1v[4], a2v[4];
#pragma unroll
    for (int c = 0; c < 4; ++c) { a1v[c] = aS[fg * 4 + c]; a2v[c] = aS[128 + fg * 4 + c]; }

#pragma unroll
    for (int rr = 0; rr < 8; ++rr) {
        int i = r0 + ig * 8 + rr;
        float4 o = make_float4(val[rr][0], val[rr][1], val[rr][2], val[rr][3]);
        *reinterpret_cast<float4*>(&Wh[(size_t)i * 128 + fg * 4]) = o;
        float v1 = val[rr][0] * a1v[0] + val[rr][1] * a1v[1] + val[rr][2] * a1v[2] + val[rr][3] * a1v[3];
        float v2 = val[rr][0] * a2v[0] + val[rr][1] * a2v[1] + val[rr][2] * a2v[2] + val[rr][3] * a2v[3];
#pragma unroll
        for (int o2 = 16; o2; o2 >>= 1) {
            v1 += __shfl_xor_sync(0xffffffffu, v1, o2);
            v2 += __shfl_xor_sync(0xffffffffu, v2, o2);
        }
        if (fg == 0) { srcp[i] = v1; dstp[i] = v2; }
    }
}

// ============ K2: per-row softmax stats ============
__global__ void k_stats(const int* __restrict__ adj,
                        const float* __restrict__ srcp, const float* __restrict__ dstp,
                        float* __restrict__ mp, float* __restrict__ rzp)
{
    int r = blockIdx.x;
    int b = r >> 9;
    int j = threadIdx.x;

    float si = srcp[r];
    int   av = adj[(size_t)r * 512 + j];
    float e  = lrelu02(si + dstp[(b << 9) + j]);
    float sc = (av > 0) ? e : -9e15f;

    __shared__ float red[16];
    __shared__ float m_sh;
    int lane = j & 31, wid = j >> 5;

    float v = sc;
#pragma unroll
    for (int o = 16; o; o >>= 1) v = fmaxf(v, __shfl_xor_sync(0xffffffffu, v, o));
    if (lane == 0) red[wid] = v;
    __syncthreads();
    if (j == 0) {
        float mm = red[0];
#pragma unroll
        for (int k = 1; k < 16; ++k) mm = fmaxf(mm, red[k]);
        m_sh = mm;
    }
    __syncthreads();

    float p = __expf(sc - m_sh);
#pragma unroll
    for (int o = 16; o; o >>= 1) p += __shfl_xor_sync(0xffffffffu, p, o);
    if (lane == 0) red[wid] = p;
    __syncthreads();
    if (j == 0) {
        float z = 0.f;
#pragma unroll
        for (int k = 0; k < 16; ++k) z += red[k];
        mp[r]  = m_sh;
        rzp[r] = 1.f / z;
    }
}

// ============ K3: attention-aggregate, packed-FMA main loop ============
constexpr int TI = 64, TJ = 32;

__global__ __launch_bounds__(256) void k_agg(
    const int* __restrict__ adj, const float* __restrict__ Whp,
    const float* __restrict__ srcp, const float* __restrict__ dstp,
    const float* __restrict__ mp, const float* __restrict__ rzp,
    float* __restrict__ outp, int ld, int col0base)
{
    __shared__ float dstS[512];
    __shared__ float srcS[TI], mS[TI], rZS[TI];
    __shared__ int   adjS[TI][TJ + 1];
    __shared__ __align__(16) float WhS[TJ][128];
    __shared__ __align__(16) float PS[TJ][TI];

    int b   = blockIdx.y;
    int i0  = blockIdx.x * TI;
    int tid = threadIdx.x;
    int fg  = tid & 31;
    int ig  = tid >> 5;

    for (int k = tid; k < 512; k += 256) dstS[k] = dstp[(b << 9) + k];
    if (tid < TI) {
        int r = (b << 9) + i0 + tid;
        srcS[tid] = srcp[r];
        mS[tid]   = mp[r];
        rZS[tid]  = rzp[r];
    }

    ull acc2[4][4];
#pragma unroll
    for (int rp = 0; rp < 4; ++rp)
#pragma unroll
        for (int c = 0; c < 4; ++c) acc2[rp][c] = 0ull;

    const size_t adj_base = ((size_t)(b << 9) + i0) * 512;
    const float4* Whg = reinterpret_cast<const float4*>(Whp) + (size_t)(b << 9) * 32;

    for (int t = 0; t < N / TJ; ++t) {
        const int tj0 = t * TJ;
        __syncthreads();

        for (int e = tid; e < TI * TJ; e += 256) {
            int ii = e >> 5, jj = e & 31;
            adjS[ii][jj] = adj[adj_base + (size_t)ii * 512 + tj0 + jj];
        }
        for (int e = tid; e < TJ * 32; e += 256) {
            int jj = e >> 5, c = e & 31;
            reinterpret_cast<float4*>(WhS)[e] = Whg[(size_t)(tj0 + jj) * 32 + c];
        }
        __syncthreads();

        {
            int ii = tid & 63;
            int jg = tid >> 6;
            float si = srcS[ii];
            float mi = mS[ii];
#pragma unroll
            for (int rr = 0; rr < 8; ++rr) {
                int j = jg * 8 + rr;
                float e2 = lrelu02(si + dstS[tj0 + j]);
                float sc = (adjS[ii][j] > 0) ? e2 : -9e15f;
                PS[j][ii] = __expf(sc - mi);
            }
        }
        __syncthreads();

#pragma unroll 8
        for (int j = 0; j < TJ; ++j) {
            float4 w = *reinterpret_cast<const float4*>(&WhS[j][fg * 4]);
            ull w0 = pack2(w.x), w1 = pack2(w.y), w2 = pack2(w.z), w3 = pack2(w.w);
            F4U p0, p1;
            p0.f = *reinterpret_cast<const float4*>(&PS[j][ig * 8]);
            p1.f = *reinterpret_cast<const float4*>(&PS[j][ig * 8 + 4]);
            ull pr[4] = {p0.u[0], p0.u[1], p1.u[0], p1.u[1]};
#pragma unroll
            for (int rp = 0; rp < 4; ++rp) {
                fma2(acc2[rp][0], pr[rp], w0);
                fma2(acc2[rp][1], pr[rp], w1);
                fma2(acc2[rp][2], pr[rp], w2);
                fma2(acc2[rp][3], pr[rp], w3);
            }
        }
    }

    float val[8][4];
#pragma unroll
    for (int rp = 0; rp < 4; ++rp)
#pragma unroll
        for (int c = 0; c < 4; ++c)
            unpack2(acc2[rp][c], val[2 * rp][c], val[2 * rp + 1][c]);

#pragma unroll
    for (int rr = 0; rr < 8; ++rr) {
        int i   = i0 + ig * 8 + rr;
        float s = rZS[ig * 8 + rr];
        float4 o;
        o.x = elu1(val[rr][0] * s);
        o.y = elu1(val[rr][1] * s);
        o.z = elu1(val[rr][2] * s);
        o.w = elu1(val[rr][3] * s);
        *reinterpret_cast<float4*>(&outp[((size_t)(b << 9) + i) * ld + col0base + fg * 4]) = o;
    }
}

// ============ K4: out = lrelu( x @ Wc + bc ), blocked GEMM ============
__global__ __launch_bounds__(256) void k_final(const float* __restrict__ Wc,
                                               const float* __restrict__ bc,
                                               float* __restrict__ out)
{
    __shared__ __align__(16) float WtS[32][128];
    __shared__ __align__(16) float htT[32][68];

    int r0   = blockIdx.y * 512 + blockIdx.x * 64;
    int col0 = blockIdx.z * 128;
    int tid  = threadIdx.x;
    int fg   = tid & 31;
    int ig   = tid >> 5;

    ull acc2[4][4];
#pragma unroll
    for (int rp = 0; rp < 4; ++rp)
#pragma unroll
        for (int c = 0; c < 4; ++c) acc2[rp][c] = 0ull;

    for (int k0 = 0; k0 < 128; k0 += 32) {
        __syncthreads();
        for (int e = tid; e < 32 * 32; e += 256) {
            int k = e >> 5, c = e & 31;
            *reinterpret_cast<float4*>(&WtS[k][c * 4]) =
                *reinterpret_cast<const float4*>(&Wc[(size_t)(k0 + k) * 256 + col0 + c * 4]);
        }
        for (int e = tid; e < 64 * 32; e += 256) {
            int ii = e >> 5, k = e & 31;
            htT[k][ii] = g_x[(size_t)(r0 + ii) * 128 + k0 + k];
        }
        __syncthreads();

#pragma unroll 8
        for (int k = 0; k < 32; ++k) {
            float4 w = *reinterpret_cast<const float4*>(&WtS[k][fg * 4]);
            ull w0 = pack2(w.x), w1 = pack2(w.y), w2 = pack2(w.z), w3 = pack2(w.w);
            F4U p0, p1;
            p0.f = *reinterpret_cast<const float4*>(&htT[k][ig * 8]);
            p1.f = *reinterpret_cast<const float4*>(&htT[k][ig * 8 + 4]);
            ull pr[4] = {p0.u[0], p0.u[1], p1.u[0], p1.u[1]};
#pragma unroll
            for (int rp = 0; rp < 4; ++rp) {
                fma2(acc2[rp][0], pr[rp], w0);
                fma2(acc2[rp][1], pr[rp], w1);
                fma2(acc2[rp][2], pr[rp], w2);
                fma2(acc2[rp][3], pr[rp], w3);
            }
        }
    }

    float val[8][4];
#pragma unroll
    for (int rp = 0; rp < 4; ++rp)
#pragma unroll
        for (int c = 0; c < 4; ++c)
            unpack2(acc2[rp][c], val[2 * rp][c], val[2 * rp + 1][c]);

    float bv[4];
#pragma unroll
    for (int c = 0; c < 4; ++c) bv[c] = bc[col0 + fg * 4 + c];

#pragma unroll
    for (int rr = 0; rr < 8; ++rr) {
        int i = r0 + ig * 8 + rr;
        float4 o;
        o.x = lrelu02(val[rr][0] + bv[0]);
        o.y = lrelu02(val[rr][1] + bv[1]);
        o.z = lrelu02(val[rr][2] + bv[2]);
        o.w = lrelu02(val[rr][3] + bv[3]);
        *reinterpret_cast<float4*>(&out[(size_t)i * 256 + col0 + fg * 4]) = o;
    }
}

// ---------------- launch ----------------
extern "C" void kernel_launch(void* const* d_in, const int* in_sizes, int n_in,
                              void* d_out, int out_size)
{
    (void)in_sizes; (void)n_in; (void)out_size;
    const float* compound = (const float*)d_in[0];   // [64,512,34]
    const int*   adj      = (const int*)d_in[1];     // [64,512,512]
    const float* Wst      = (const float*)d_in[2];   // [3,34,128]
    const float* ast      = (const float*)d_in[3];   // [3,256,1]
    const float* Wout     = (const float*)d_in[4];   // [384,128]
    const float* aout     = (const float*)d_in[5];   // [256,1]
    const float* Wc       = (const float*)d_in[6];   // [128,256]
    const float* bc       = (const float*)d_in[7];   // [256]
    float* out = (float*)d_out;                      // [64,512,256]

    float* g_Wh3_p;   cudaGetSymbolAddress((void**)&g_Wh3_p,  g_Wh3);
    float* g_heads_p; cudaGetSymbolAddress((void**)&g_heads_p, g_heads);
    float* g_x_p;     cudaGetSymbolAddress((void**)&g_x_p,    g_x);
    float* g_src_p;   cudaGetSymbolAddress((void**)&g_src_p,  g_src3);
    float* g_dst_p;   cudaGetSymbolAddress((void**)&g_dst_p,  g_dst3);
    float* g_m_p;     cudaGetSymbolAddress((void**)&g_m_p,    g_m3);
    float* g_rz_p;    cudaGetSymbolAddress((void**)&g_rz_p,   g_rz3);

    dim3 tile_grid(N / 64, B);

    // all 3 input-layer projections in one launch (grid.z = layer)
    k_proj<34, 34><<<dim3(N / 64, B, 3), 256>>>(
        compound, 34, Wst, ast, g_Wh3_p, g_src_p, g_dst_p);

    for (int l = 0; l < 3; ++l) {
        k_stats<<<R, 512>>>(adj, g_src_p + (size_t)l * R, g_dst_p + (size_t)l * R,
                            g_m_p + (size_t)l * R, g_rz_p + (size_t)l * R);
        k_agg<<<tile_grid, 256>>>(adj, g_Wh3_p + (size_t)l * R * 128,
                                  g_src_p + (size_t)l * R, g_dst_p + (size_t)l * R,
                                  g_m_p + (size_t)l * R, g_rz_p + (size_t)l * R,
                                  g_heads_p, 384, l * 128);
    }

    // out-layer projection on concatenated heads
    k_proj<384, 32><<<dim3(N / 64, B, 1), 256>>>(
        g_heads_p, 384, Wout, aout,
        g_Wh3_p + (size_t)3 * R * 128, g_src_p + (size_t)3 * R, g_dst_p + (size_t)3 * R);

    k_stats<<<R, 512>>>(adj, g_src_p + (size_t)3 * R, g_dst_p + (size_t)3 * R,
                        g_m_p + (size_t)3 * R, g_rz_p + (size_t)3 * R);
    k_agg<<<tile_grid, 256>>>(adj, g_Wh3_p + (size_t)3 * R * 128,
                              g_src_p + (size_t)3 * R, g_dst_p + (size_t)3 * R,
                              g_m_p + (size_t)3 * R, g_rz_p + (size_t)3 * R,
                              g_x_p, 128, 0);

    k_final<<<dim3(N / 64, B, 2), 256>>>(Wc, bc, out);
}